// round 9
// baseline (speedup 1.0000x reference)
#include <cuda_runtime.h>

#define B 64
#define BH 32               // b's per work item (half of B)
#define C 1501
#define NW (2 * C)          // work items: (c, half)
#define D 2048
#define D4 (D / 4)          // 512 float4 per row
#define TOT4 (C * D4)       // 768512 float4 per [C,D] tile
#define ALPHA 0.01f
#define EPS 1e-7f
#define GRID 296            // 2 persistent blocks per SM (148 SMs)

// Persistent fused kernel. Each of 296 blocks loops over (c, half) items.
//  - cls loaded/decoded ONCE per block (not per item)
//  - next item's memory row + x row prefetched before current item's stores,
//    hiding load latency under the streaming-store drain; no per-wave
//    prologue bubbles -> DRAM write queues stay fed.
__global__ __launch_bounds__(512) void fused_kernel(
    const float4* __restrict__ x4,
    const float4* __restrict__ mem4,
    const int* __restrict__ cls_raw,
    float4* __restrict__ sel4,
    float4* __restrict__ rep4,
    float4* __restrict__ nm4) {
    const int t = threadIdx.x;  // 0..511

    __shared__ int s_cls[B];
    __shared__ int s_is64;
    __shared__ float s_red[16];

    if (t == 0) {
        // int64 little-endian: odd words within the first 64 are high halves
        // of cls[0..31], all zero since 0 <= cls < 1501. int32: random ids.
        int any = 0;
#pragma unroll
        for (int i = 1; i < B; i += 2) any |= cls_raw[i];
        s_is64 = (any == 0) ? 1 : 0;
    }
    __syncthreads();
    if (t < B) s_cls[t] = s_is64 ? cls_raw[2 * t] : cls_raw[t];
    __syncthreads();

    // ---- prologue: load state for first work item ----
    int wi = blockIdx.x;
    int c = wi >> 1;
    int half = wi & 1;
    float4 m, xv;
    int ow = -1;
    if (wi < NW) {
        m = __ldg(mem4 + (size_t)c * D4 + t);
#pragma unroll
        for (int b = 0; b < B; b++)
            if (s_cls[b] == c) ow = b;  // last write wins -> max b
        if (ow >= 0) xv = __ldg(x4 + (size_t)ow * D4 + t);
    }

    while (wi < NW) {
        // ---- prefetch next item (loads in flight during current stores) ----
        const int wn = wi + GRID;
        const int cn = wn >> 1;
        const int hn = wn & 1;
        float4 mn, xvn;
        int own = -1;
        if (wn < NW) {
            mn = __ldg(mem4 + (size_t)cn * D4 + t);
#pragma unroll
            for (int b = 0; b < B; b++)
                if (s_cls[b] == cn) own = b;
            if (own >= 0) xvn = __ldg(x4 + (size_t)own * D4 + t);
        }

        // ---- current item: stream BH copies of tmp_memory[c] ----
        const float4 v = (ow >= 0) ? xv : m;
        float4* dst = rep4 + (size_t)(half * BH) * TOT4 + (size_t)c * D4 + t;
#pragma unroll 8
        for (int b = 0; b < BH; b++) {
            __stcs(dst, v);
            dst += TOT4;
        }

        // ---- epilogue for half==0: selected rows + new_mem row ----
        if (half == 0) {
            // selected[b] = ORIGINAL memory[cls[b]] for every matching b
#pragma unroll
            for (int b = 0; b < B; b++)
                if (s_cls[b] == c) sel4[(size_t)b * D4 + t] = m;

            float4 y;
            y.x = m.x * (1.f - ALPHA) + v.x * ALPHA;
            y.y = m.y * (1.f - ALPHA) + v.y * ALPHA;
            y.z = m.z * (1.f - ALPHA) + v.z * ALPHA;
            y.w = m.w * (1.f - ALPHA) + v.w * ALPHA;
            float ss = y.x * y.x + y.y * y.y + y.z * y.z + y.w * y.w;
#pragma unroll
            for (int off = 16; off > 0; off >>= 1)
                ss += __shfl_xor_sync(0xffffffffu, ss, off);
            if ((t & 31) == 0) s_red[t >> 5] = ss;
            __syncthreads();
            if (t < 32) {
                float u = (t < 16) ? s_red[t] : 0.f;
#pragma unroll
                for (int off = 8; off > 0; off >>= 1)
                    u += __shfl_xor_sync(0xffffffffu, u, off);
                if (t == 0) s_red[0] = u;
            }
            __syncthreads();
            const float inv = 1.f / (sqrtf(s_red[0]) + EPS);
            y.x *= inv; y.y *= inv; y.z *= inv; y.w *= inv;
            nm4[(size_t)c * D4 + t] = y;
        }

        // ---- rotate state ----
        wi = wn; c = cn; half = hn; m = mn; ow = own; xv = xvn;
    }
}

extern "C" void kernel_launch(void* const* d_in, const int* in_sizes, int n_in,
                              void* d_out, int out_size) {
    const float* x = (const float*)d_in[0];
    const int* cls = (const int*)d_in[1];
    const float* memory = (const float*)d_in[2];
    float* out = (float*)d_out;

    float* sel = out;                    // [B, D]
    float* rep = out + (size_t)B * D;    // [B, C, D]
    float* nm = rep + (size_t)B * C * D; // [C, D]

    fused_kernel<<<GRID, 512>>>((const float4*)x, (const float4*)memory, cls,
                                (float4*)sel, (float4*)rep, (float4*)nm);
}

// round 11
// speedup vs baseline: 1.1816x; 1.1816x over previous
#include <cuda_runtime.h>

#define B 64
#define BQ 16               // b's per work item (quarter of B)
#define C 1501
#define D 2048
#define D4 (D / 4)          // 512 float4 per row
#define TOT4 (C * D4)       // 768512 float4 per [C,D] tile
#define ALPHA 0.01f
#define EPS 1e-7f

// One block per (memory row c, quarter of the B repeat copies).
// grid = (C, 4): 40 waves, fine-grained tail.
// The memory-row load is issued BEFORE the cls smem setup so its DRAM
// latency hides under the cls load + barrier instead of delaying the
// first streaming store.
__global__ __launch_bounds__(512) void fused_kernel(
    const float4* __restrict__ x4,
    const float4* __restrict__ mem4,
    const int* __restrict__ cls_raw,
    float4* __restrict__ sel4,
    float4* __restrict__ rep4,
    float4* __restrict__ nm4) {
    const int c = blockIdx.x;
    const int q = blockIdx.y;          // 0..3
    const int t = threadIdx.x;         // 0..511

    __shared__ int s_cls[B];
    __shared__ int s_is64;
    __shared__ float s_red[16];

    // Independent of cls: issue immediately so latency overlaps the setup.
    const size_t row_off = (size_t)c * D4 + t;
    const float4 m = __ldg(mem4 + row_off);

    // Dtype detect in parallel (warp 0): int64 little-endian odd words are
    // high halves of cls[0..31], all zero since 0 <= cls < 1501.
    if (t < 32) {
        int hi = cls_raw[2 * t + 1];
        int any = __any_sync(0xffffffffu, hi != 0);
        if (t == 0) s_is64 = any ? 0 : 1;
    }
    __syncthreads();
    if (t < B) s_cls[t] = s_is64 ? cls_raw[2 * t] : cls_raw[t];
    __syncthreads();

    // Owner scan (last write wins -> max b).
    int ow = -1;
#pragma unroll
    for (int b = 0; b < B; b++)
        if (s_cls[b] == c) ow = b;

    const float4 v = (ow >= 0) ? __ldg(x4 + (size_t)ow * D4 + t) : m;

    // Streaming writes: this block's BQ copies of tmp_memory[c].
    float4* dst = rep4 + (size_t)(q * BQ) * TOT4 + row_off;
#pragma unroll 8
    for (int b = 0; b < BQ; b++) {
        __stcs(dst, v);
        dst += TOT4;
    }

    if (q != 0) return;

    // selected[b] = ORIGINAL memory[cls[b]] for every matching b.
#pragma unroll
    for (int b = 0; b < B; b++)
        if (s_cls[b] == c) sel4[(size_t)b * D4 + t] = m;

    // EMA + L2 normalize for new_mem[c].
    float4 y;
    y.x = m.x * (1.f - ALPHA) + v.x * ALPHA;
    y.y = m.y * (1.f - ALPHA) + v.y * ALPHA;
    y.z = m.z * (1.f - ALPHA) + v.z * ALPHA;
    y.w = m.w * (1.f - ALPHA) + v.w * ALPHA;
    float ss = y.x * y.x + y.y * y.y + y.z * y.z + y.w * y.w;

#pragma unroll
    for (int off = 16; off > 0; off >>= 1)
        ss += __shfl_xor_sync(0xffffffffu, ss, off);
    if ((t & 31) == 0) s_red[t >> 5] = ss;
    __syncthreads();
    if (t < 32) {
        float u = (t < 16) ? s_red[t] : 0.f;
#pragma unroll
        for (int off = 8; off > 0; off >>= 1)
            u += __shfl_xor_sync(0xffffffffu, u, off);
        if (t == 0) s_red[0] = u;
    }
    __syncthreads();

    const float inv = 1.f / (sqrtf(s_red[0]) + EPS);
    y.x *= inv; y.y *= inv; y.z *= inv; y.w *= inv;
    nm4[row_off] = y;
}

extern "C" void kernel_launch(void* const* d_in, const int* in_sizes, int n_in,
                              void* d_out, int out_size) {
    const float* x = (const float*)d_in[0];
    const int* cls = (const int*)d_in[1];
    const float* memory = (const float*)d_in[2];
    float* out = (float*)d_out;

    float* sel = out;                    // [B, D]
    float* rep = out + (size_t)B * D;    // [B, C, D]
    float* nm = rep + (size_t)B * C * D; // [C, D]

    dim3 grid(C, 4);
    fused_kernel<<<grid, 512>>>((const float4*)x, (const float4*)memory, cls,
                                (float4*)sel, (float4*)rep, (float4*)nm);
}